// round 6
// baseline (speedup 1.0000x reference)
#include <cuda_runtime.h>
#include <stdint.h>

// ---------------- problem constants ----------------
#define T_STEPS 16
#define NNODES  50000
#define IN_F    128
#define B_N     4096
#define S1_N    5
#define S2_N    2
#define H1_N    128
#define H2_N    64
#define C_OUT   32
#define K_CONV  5
#define R1      (B_N + B_N * S1_N)   // 24576 layer-1 rows per timestep
#define KTOT    256                  // layer-1 K ([self 128 | neigh 128])
#define APAD    44                   // smem row stride (floats): 16B-aligned, conflict-free
#define EPS_RESCUE 1e-4f             // |u-thr| window recomputed in exact fp32

typedef unsigned long long ull;

// ---------------- scratch (static device memory; no allocations) ----------------
__device__ uint8_t g_s1[(size_t)T_STEPS * R1 * H1_N];     // ~50 MB layer-1 spikes
__device__ uint8_t g_s2[(size_t)T_STEPS * B_N * H2_N];    // ~4 MB  layer-2 spikes
__device__ float   g_A[H2_N * T_STEPS];                   // folded delay+conv weights
__device__ float   g_W1hi[H1_N * KTOT];                   // W1^T [n][k], tf32-rounded hi
__device__ float   g_W1lo[H1_N * KTOT];                   // W1^T [n][k], tf32-rounded residual

// ---------------- helpers ----------------
__device__ __forceinline__ float tf32r(float x) {
    uint32_t u;
    asm("cvt.rna.tf32.f32 %0, %1;" : "=r"(u) : "f"(x));
    return __uint_as_float(u);
}

#define MMA_TF32(d, a, b0, b1)                                            \
    asm volatile("mma.sync.aligned.m16n8k8.row.col.f32.tf32.tf32.f32 "    \
                 "{%0,%1,%2,%3}, {%4,%5,%6,%7}, {%8,%9}, {%0,%1,%2,%3};"  \
                 : "+f"((d)[0]), "+f"((d)[1]), "+f"((d)[2]), "+f"((d)[3]) \
                 : "r"((a)[0]), "r"((a)[1]), "r"((a)[2]), "r"((a)[3]),    \
                   "r"(b0), "r"(b1))

// packed fp32x2 (layer2)
__device__ __forceinline__ ull fma2(ull a, ull b, ull c) {
    ull d;
    asm("fma.rn.f32x2 %0, %1, %2, %3;" : "=l"(d) : "l"(a), "l"(b), "l"(c));
    return d;
}
__device__ __forceinline__ ull dup2(float v) {
    ull r;
    asm("mov.b64 %0, {%1, %1};" : "=l"(r) : "f"(v));
    return r;
}
__device__ __forceinline__ float lo2(ull v) { return __uint_as_float((unsigned)(v)); }
__device__ __forceinline__ float hi2(ull v) { return __uint_as_float((unsigned)(v >> 32)); }

// ---------------- exact fp32 rescue for near-threshold layer-1 outputs ----------
// Recomputes u1[row][col] from scratch (gather + mean + dual dot) in fp32.
// Cold path: called for ~1 in 20k outputs. __noinline__ keeps hot regs clean.
__device__ __noinline__ bool rescue_dot(const float* __restrict__ xt,
                                        const int* s_self, const int* s_nbr,
                                        int typeA, int r, int col,
                                        const float* __restrict__ W1s,
                                        const float* __restrict__ W1n,
                                        float thr) {
    const float* xs = xt + (size_t)s_self[r] * IN_F;
    float u = 0.0f;
    #pragma unroll 4
    for (int k = 0; k < IN_F; k++)
        u = fmaf(xs[k], W1s[(size_t)k * H1_N + col], u);
    const int   S    = typeA ? S1_N : S2_N;
    const float invS = typeA ? 0.2f : 0.5f;
    #pragma unroll 4
    for (int k = 0; k < IN_F; k++) {
        float m = 0.0f;
        for (int s = 0; s < S; s++)
            m += xt[(size_t)s_nbr[r * S + s] * IN_F + k];
        u = fmaf(m * invS, W1n[(size_t)k * H1_N + col], u);
    }
    return u >= thr;
}

// ============================================================================
// Kernel 0a: fold softmax(delay_w) + depthwise-conv SAME + time-mean into A[c][t].
// ============================================================================
__global__ void prepA_kernel(const float* __restrict__ delay_w,
                             const float* __restrict__ dwk) {
    int c = threadIdx.x;
    if (c >= H2_N) return;
    int g = c >> 3;
    float w0 = delay_w[g * 3 + 0], w1 = delay_w[g * 3 + 1], w2 = delay_w[g * 3 + 2];
    float mx = fmaxf(w0, fmaxf(w1, w2));
    float e0 = expf(w0 - mx), e1 = expf(w1 - mx), e2 = expf(w2 - mx);
    float inv = 1.0f / (e0 + e1 + e2);
    e0 *= inv; e1 *= inv; e2 *= inv;

    float coef[T_STEPS];
    #pragma unroll
    for (int tau = 0; tau < T_STEPS; tau++) {
        int kmin = (tau - 13 > 0) ? (tau - 13) : 0;
        int kmax = (tau + 2 < 4) ? (tau + 2) : 4;
        float s = 0.0f;
        for (int k = kmin; k <= kmax; k++) s += dwk[c * K_CONV + k];
        coef[tau] = s * (1.0f / (float)T_STEPS);
    }
    #pragma unroll
    for (int t = 0; t < T_STEPS; t++) {
        float a = 0.0f;
        if (t + 1 < T_STEPS) a += e0 * coef[t + 1];
        if (t + 3 < T_STEPS) a += e1 * coef[t + 3];
        if (t + 5 < T_STEPS) a += e2 * coef[t + 5];
        g_A[c * T_STEPS + t] = a;
    }
}

// ============================================================================
// Kernel 0b: pre-split + transpose W1 into [n][k] tf32 hi/lo arrays.
// ============================================================================
__global__ void prepW1_kernel(const float* __restrict__ W1s,
                              const float* __restrict__ W1n) {
    int idx = blockIdx.x * 256 + threadIdx.x;   // 32768 total
    int n = idx & (H1_N - 1);
    int k = idx >> 7;
    float w = (k < IN_F) ? W1s[(size_t)k * H1_N + n]
                         : W1n[(size_t)(k - IN_F) * H1_N + n];
    float h = tf32r(w);
    g_W1hi[n * KTOT + k] = h;
    g_W1lo[n * KTOT + k] = tf32r(w - h);
}

// ============================================================================
// Kernel 1: fused gather + mean + tf32x3 mma.sync GEMM (128x128xK256) + spike,
// with exact-fp32 rescue of outputs within EPS_RESCUE of the threshold.
// ============================================================================
__global__ void __launch_bounds__(256, 2)
layer1_kernel(const float* __restrict__ x, const int* __restrict__ nodes,
              const int* __restrict__ nbr1, const int* __restrict__ nbr2,
              const float* __restrict__ b1,
              const float* __restrict__ W1s, const float* __restrict__ W1n) {
    extern __shared__ float sm[];
    float* Ah = sm;                       // 128*APAD
    float* Al = Ah + 128 * APAD;
    float* Bh = Al + 128 * APAD;
    float* Bl = Bh + 128 * APAD;
    __shared__ int s_self[128];
    __shared__ int s_nbr[128 * S1_N];
    __shared__ float s_thr[128];

    const int tid = threadIdx.x;
    const int wid = tid >> 5;
    const int lane = tid & 31;
    const int t = blockIdx.y;
    const int blk = blockIdx.x;               // 0..191
    const int typeA = (blk < (B_N / 128));
    const int rowbase = blk * 128;

    // ---- index + threshold stage ----
    if (tid < 128) s_thr[tid] = 1.0f - b1[tid];
    if (typeA) {
        if (tid < 128) s_self[tid] = nodes[rowbase + tid];
        for (int q = tid; q < 128 * S1_N; q += 256) {
            int r = q / S1_N, s = q - r * S1_N;
            s_nbr[q] = nbr1[((size_t)t * B_N + rowbase + r) * S1_N + s];
        }
    } else {
        const int j0 = rowbase - B_N;
        if (tid < 128) s_self[tid] = nbr1[(size_t)t * B_N * S1_N + j0 + tid];
        for (int q = tid; q < 128 * S2_N; q += 256) {
            int r = q >> 1, s = q & 1;
            s_nbr[q] = nbr2[((size_t)t * (B_N * S1_N) + j0 + r) * S2_N + s];
        }
    }

    const float* xt = x + (size_t)t * NNODES * IN_F;
    const int gr = tid >> 1;                  // gather row / n index 0..127
    const int gq = (tid & 1) * 4;             // first of 4 float4 quads

    // warp tile 32x64: 4 M-groups x 2 N-groups
    const int mbase = (wid & 3) * 32;
    const int nbase = (wid >> 2) * 64;
    const int g  = lane >> 2;                 // 0..7
    const int tg = lane & 3;                  // 0..3

    float acc[2][8][4];
    #pragma unroll
    for (int mt = 0; mt < 2; mt++)
        #pragma unroll
        for (int j = 0; j < 8; j++)
            #pragma unroll
            for (int c = 0; c < 4; c++) acc[mt][j][c] = 0.0f;

    const uint32_t* Ah_u = (const uint32_t*)Ah;
    const uint32_t* Al_u = (const uint32_t*)Al;
    const uint32_t* Bh_u = (const uint32_t*)Bh;
    const uint32_t* Bl_u = (const uint32_t*)Bl;

    for (int kc = 0; kc < 8; kc++) {
        __syncthreads();   // smem free (also orders index stage on iter 0)
        const int f0 = (kc & 3) * 32;
        // ---- A gather + Dekker split ----
        if (kc < 4) {
            const float* src = xt + (size_t)s_self[gr] * IN_F + f0;
            #pragma unroll
            for (int i = 0; i < 4; i++) {
                float4 v = *(const float4*)(src + (gq + i) * 4);
                float hx = tf32r(v.x), hy = tf32r(v.y), hz = tf32r(v.z), hw = tf32r(v.w);
                int o = gr * APAD + (gq + i) * 4;
                *(float4*)(Ah + o) = make_float4(hx, hy, hz, hw);
                *(float4*)(Al + o) = make_float4(tf32r(v.x - hx), tf32r(v.y - hy),
                                                 tf32r(v.z - hz), tf32r(v.w - hw));
            }
        } else {
            const int   S    = typeA ? S1_N : S2_N;
            const float invS = typeA ? 0.2f : 0.5f;
            #pragma unroll
            for (int i = 0; i < 4; i++) {
                float ax = 0.f, ay = 0.f, az = 0.f, aw = 0.f;
                for (int s = 0; s < S; s++) {
                    float4 v = *(const float4*)(xt + (size_t)s_nbr[gr * S + s] * IN_F
                                                + f0 + (gq + i) * 4);
                    ax += v.x; ay += v.y; az += v.z; aw += v.w;
                }
                ax *= invS; ay *= invS; az *= invS; aw *= invS;
                float hx = tf32r(ax), hy = tf32r(ay), hz = tf32r(az), hw = tf32r(aw);
                int o = gr * APAD + (gq + i) * 4;
                *(float4*)(Ah + o) = make_float4(hx, hy, hz, hw);
                *(float4*)(Al + o) = make_float4(tf32r(ax - hx), tf32r(ay - hy),
                                                 tf32r(az - hz), tf32r(aw - hw));
            }
        }
        // ---- B stage (pre-split, pre-transposed) ----
        {
            const float* sh = g_W1hi + gr * KTOT + kc * 32;
            const float* sl = g_W1lo + gr * KTOT + kc * 32;
            #pragma unroll
            for (int i = 0; i < 4; i++) {
                int o = gr * APAD + (gq + i) * 4;
                *(float4*)(Bh + o) = *(const float4*)(sh + (gq + i) * 4);
                *(float4*)(Bl + o) = *(const float4*)(sl + (gq + i) * 4);
            }
        }
        __syncthreads();

        // ---- mma over 4 k8 steps, 3 precision passes ----
        #pragma unroll
        for (int k8 = 0; k8 < 4; k8++) {
            const int kb = k8 * 8;
            uint32_t ah[2][4], al[2][4];
            #pragma unroll
            for (int mt = 0; mt < 2; mt++) {
                int r0 = (mbase + 16 * mt + g) * APAD + kb + tg;
                int r8 = r0 + 8 * APAD;
                ah[mt][0] = Ah_u[r0];     ah[mt][1] = Ah_u[r8];
                ah[mt][2] = Ah_u[r0 + 4]; ah[mt][3] = Ah_u[r8 + 4];
                al[mt][0] = Al_u[r0];     al[mt][1] = Al_u[r8];
                al[mt][2] = Al_u[r0 + 4]; al[mt][3] = Al_u[r8 + 4];
            }
            #pragma unroll
            for (int j = 0; j < 8; j++) {
                int bi = (nbase + 8 * j + g) * APAD + kb + tg;
                uint32_t bh0 = Bh_u[bi], bh1 = Bh_u[bi + 4];
                uint32_t bl0 = Bl_u[bi], bl1 = Bl_u[bi + 4];
                #pragma unroll
                for (int mt = 0; mt < 2; mt++) {
                    MMA_TF32(acc[mt][j], ah[mt], bh0, bh1);   // hh
                    MMA_TF32(acc[mt][j], ah[mt], bl0, bl1);   // hl
                    MMA_TF32(acc[mt][j], al[mt], bh0, bh1);   // lh
                }
            }
        }
    }

    // ---- epilogue: threshold (+ exact rescue) -> byte-stage -> coalesced store ----
    __syncthreads();
    uint8_t* sbytes = (uint8_t*)sm;           // reuse Ah region (16 KB)
    #pragma unroll
    for (int mt = 0; mt < 2; mt++) {
        int R0 = mbase + 16 * mt + g;
        #pragma unroll
        for (int j = 0; j < 8; j++) {
            int C0 = nbase + 8 * j + 2 * tg;
            #pragma unroll
            for (int c = 0; c < 4; c++) {
                int R = R0 + (c >> 1) * 8;
                int C = C0 + (c & 1);
                float thr = s_thr[C];
                float d = acc[mt][j][c] - thr;
                bool sp;
                if (fabsf(d) < EPS_RESCUE) {
                    sp = rescue_dot(xt, s_self, s_nbr, typeA, R, C, W1s, W1n, thr);
                } else {
                    sp = (d >= 0.0f);
                }
                sbytes[R * 128 + C] = sp ? 1 : 0;
            }
        }
    }
    __syncthreads();
    uint8_t* dst = g_s1 + ((size_t)t * R1 + rowbase) * H1_N;
    #pragma unroll
    for (int i = 0; i < 4; i++) {
        int o = (tid + i * 256) * 16;
        *(uint4*)(dst + o) = *(const uint4*)(sbytes + o);
    }
}

// ============================================================================
// Kernel 2: layer-2 GEMM, packed fp32x2. u2 = [g0 | mean(g1)] @ [W2s;W2n] + b2.
// ============================================================================
__global__ void __launch_bounds__(256, 1)
layer2_kernel(const float* __restrict__ W2s, const float* __restrict__ W2n,
              const float* __restrict__ b2) {
    extern __shared__ float sm[];
    float* Zt = sm;                  // [256][64] k-major
    float* Wt = sm + 256 * 64;       // [256][64]
    const int tid = threadIdx.x;
    const int t = blockIdx.y;
    const int b0 = blockIdx.x * 64;

    const uint8_t* s1t = g_s1 + (size_t)t * R1 * H1_N;
    const int r  = tid & 63;
    const int w0 = tid >> 6;
    for (int w = w0; w < 32; w += 4) {
        uint32_t gw = *(const uint32_t*)(s1t + (size_t)(b0 + r) * H1_N + w * 4);
        uint32_t mw = 0;   // bytes are 0/1; sum of 5 fits in a byte
        #pragma unroll
        for (int s = 0; s < S1_N; s++)
            mw += *(const uint32_t*)(s1t + (size_t)(B_N + (b0 + r) * S1_N + s) * H1_N + w * 4);
        int k = w * 4;
        Zt[(k + 0) * 64 + r] = (float)(gw & 0xffu);
        Zt[(k + 1) * 64 + r] = (float)((gw >> 8) & 0xffu);
        Zt[(k + 2) * 64 + r] = (float)((gw >> 16) & 0xffu);
        Zt[(k + 3) * 64 + r] = (float)(gw >> 24);
        Zt[(H1_N + k + 0) * 64 + r] = 0.2f * (float)(mw & 0xffu);
        Zt[(H1_N + k + 1) * 64 + r] = 0.2f * (float)((mw >> 8) & 0xffu);
        Zt[(H1_N + k + 2) * 64 + r] = 0.2f * (float)((mw >> 16) & 0xffu);
        Zt[(H1_N + k + 3) * 64 + r] = 0.2f * (float)(mw >> 24);
    }
    for (int idx = tid; idx < 256 * 16; idx += 256) {
        int kr = idx >> 4, c4 = idx & 15;
        const float* src = (kr < H1_N) ? (W2s + (size_t)kr * H2_N)
                                       : (W2n + (size_t)(kr - H1_N) * H2_N);
        *(float4*)&Wt[kr * 64 + c4 * 4] = *(const float4*)(src + c4 * 4);
    }
    __syncthreads();

    const int r0 = (tid & 15) * 4;
    const int c0 = (tid >> 4) * 4;

    ull acc[2][4];
    #pragma unroll
    for (int i = 0; i < 2; i++)
        #pragma unroll
        for (int j = 0; j < 4; j++) acc[i][j] = 0ull;

    #pragma unroll 8
    for (int k = 0; k < 256; k++) {
        const ull* za = (const ull*)&Zt[k * 64 + r0];
        ull a0 = za[0], a1 = za[1];
        float4 b4 = *(const float4*)&Wt[k * 64 + c0];
        ull bd0 = dup2(b4.x), bd1 = dup2(b4.y), bd2 = dup2(b4.z), bd3 = dup2(b4.w);
        acc[0][0] = fma2(a0, bd0, acc[0][0]);
        acc[1][0] = fma2(a1, bd0, acc[1][0]);
        acc[0][1] = fma2(a0, bd1, acc[0][1]);
        acc[1][1] = fma2(a1, bd1, acc[1][1]);
        acc[0][2] = fma2(a0, bd2, acc[0][2]);
        acc[1][2] = fma2(a1, bd2, acc[1][2]);
        acc[0][3] = fma2(a0, bd3, acc[0][3]);
        acc[1][3] = fma2(a1, bd3, acc[1][3]);
    }

    float bb[4];
    #pragma unroll
    for (int j = 0; j < 4; j++) bb[j] = b2[c0 + j];
    #pragma unroll
    for (int i = 0; i < 2; i++) {
        int b = b0 + r0 + 2 * i;
        uint32_t pk0 = 0, pk1 = 0;
        #pragma unroll
        for (int j = 0; j < 4; j++) {
            if (lo2(acc[i][j]) + bb[j] >= 1.0f) pk0 |= (1u << (8 * j));
            if (hi2(acc[i][j]) + bb[j] >= 1.0f) pk1 |= (1u << (8 * j));
        }
        *(uint32_t*)(g_s2 + ((size_t)t * B_N + b)     * H2_N + c0) = pk0;
        *(uint32_t*)(g_s2 + ((size_t)t * B_N + b + 1) * H2_N + c0) = pk1;
    }
}

// ============================================================================
// Kernel 3: readout. out[b,j] = ro_b[j] + sum_c (sum_t s2[t,b,c]*A[c,t]) ro_W[c,j]
// ============================================================================
__global__ void __launch_bounds__(256)
readout_kernel(const float* __restrict__ ro_W, const float* __restrict__ ro_b,
               float* __restrict__ out) {
    __shared__ float Msm[8][64];
    const int warp = threadIdx.x >> 5;
    const int lane = threadIdx.x & 31;
    const int b = blockIdx.x * 8 + warp;

    float m0 = 0.f, m1 = 0.f;
    #pragma unroll
    for (int t = 0; t < T_STEPS; t++) {
        const uint8_t* row = g_s2 + ((size_t)t * B_N + b) * H2_N;
        m0 = fmaf((float)row[lane],      g_A[lane * T_STEPS + t],        m0);
        m1 = fmaf((float)row[lane + 32], g_A[(lane + 32) * T_STEPS + t], m1);
    }
    Msm[warp][lane] = m0;
    Msm[warp][lane + 32] = m1;
    __syncwarp();

    float o = ro_b[lane];
    #pragma unroll
    for (int c = 0; c < 64; c++)
        o = fmaf(Msm[warp][c], ro_W[c * C_OUT + lane], o);
    out[(size_t)b * C_OUT + lane] = o;
}

// ============================================================================
extern "C" void kernel_launch(void* const* d_in, const int* in_sizes, int n_in,
                              void* d_out, int out_size) {
    const float* x    = (const float*)d_in[0];
    const int*   nodes= (const int*)  d_in[1];
    const int*   nbr1 = (const int*)  d_in[2];
    const int*   nbr2 = (const int*)  d_in[3];
    const float* W1s  = (const float*)d_in[4];
    const float* W1n  = (const float*)d_in[5];
    const float* b1   = (const float*)d_in[6];
    const float* W2s  = (const float*)d_in[7];
    const float* W2n  = (const float*)d_in[8];
    const float* b2   = (const float*)d_in[9];
    const float* dlw  = (const float*)d_in[10];
    const float* dwk  = (const float*)d_in[11];
    const float* roW  = (const float*)d_in[12];
    const float* rob  = (const float*)d_in[13];
    float* out = (float*)d_out;

    const int l1_smem = 4 * 128 * APAD * 4;   // 90112 B
    cudaFuncSetAttribute(layer1_kernel, cudaFuncAttributeMaxDynamicSharedMemorySize, l1_smem);
    cudaFuncSetAttribute(layer2_kernel, cudaFuncAttributeMaxDynamicSharedMemorySize, 131072);

    prepA_kernel<<<1, 64>>>(dlw, dwk);
    prepW1_kernel<<<128, 256>>>(W1s, W1n);
    layer1_kernel<<<dim3(R1 / 128, T_STEPS), 256, l1_smem>>>(x, nodes, nbr1, nbr2, b1, W1s, W1n);
    layer2_kernel<<<dim3(B_N / 64, T_STEPS), 256, 131072>>>(W2s, W2n, b2);
    readout_kernel<<<B_N / 8, 256>>>(roW, rob, out);
}

// round 8
// speedup vs baseline: 1.0659x; 1.0659x over previous
#include <cuda_runtime.h>
#include <stdint.h>

// ---------------- problem constants ----------------
#define T_STEPS 16
#define NNODES  50000
#define IN_F    128
#define B_N     4096
#define S1_N    5
#define S2_N    2
#define H1_N    128
#define H2_N    64
#define C_OUT   32
#define K_CONV  5
#define R1      (B_N + B_N * S1_N)   // 24576 layer-1 rows per timestep
#define KTOT    256                  // layer-1 K ([self 128 | neigh 128])
#define APAD    44                   // tensor-path smem row stride (floats)
#define EPS_RESCUE 1e-4f             // |u-thr| window recomputed in exact fp32
#define SCALAR_OF_16 9               // blocks with (blk&15) < 9 take scalar path

typedef unsigned long long ull;

// ---------------- scratch (static device memory; no allocations) ----------------
__device__ uint8_t g_s1[(size_t)T_STEPS * R1 * H1_N];     // ~50 MB layer-1 spikes
__device__ uint8_t g_s2[(size_t)T_STEPS * B_N * H2_N];    // ~4 MB  layer-2 spikes
__device__ float   g_A[H2_N * T_STEPS];                   // folded delay+conv weights
__device__ float   g_W1hi[H1_N * KTOT];                   // W1^T [n][k], tf32 hi
__device__ float   g_W1lo[H1_N * KTOT];                   // W1^T [n][k], tf32 residual

// ---------------- helpers ----------------
__device__ __forceinline__ float tf32r(float x) {
    uint32_t u;
    asm("cvt.rna.tf32.f32 %0, %1;" : "=r"(u) : "f"(x));
    return __uint_as_float(u);
}

#define MMA_TF32(d, a, b0, b1)                                            \
    asm volatile("mma.sync.aligned.m16n8k8.row.col.f32.tf32.tf32.f32 "    \
                 "{%0,%1,%2,%3}, {%4,%5,%6,%7}, {%8,%9}, {%0,%1,%2,%3};"  \
                 : "+f"((d)[0]), "+f"((d)[1]), "+f"((d)[2]), "+f"((d)[3]) \
                 : "r"((a)[0]), "r"((a)[1]), "r"((a)[2]), "r"((a)[3]),    \
                   "r"(b0), "r"(b1))

__device__ __forceinline__ ull fma2(ull a, ull b, ull c) {
    ull d;
    asm("fma.rn.f32x2 %0, %1, %2, %3;" : "=l"(d) : "l"(a), "l"(b), "l"(c));
    return d;
}
__device__ __forceinline__ ull dup2(float v) {
    ull r;
    asm("mov.b64 %0, {%1, %1};" : "=l"(r) : "f"(v));
    return r;
}
__device__ __forceinline__ float lo2(ull v) { return __uint_as_float((unsigned)(v)); }
__device__ __forceinline__ float hi2(ull v) { return __uint_as_float((unsigned)(v >> 32)); }

// ---------------- exact fp32 rescue for near-threshold layer-1 outputs --------
__device__ __noinline__ bool rescue_dot(const float* __restrict__ xt,
                                        const int* s_self, const int* s_nbr,
                                        int typeA, int r, int col,
                                        const float* __restrict__ W1s,
                                        const float* __restrict__ W1n,
                                        float thr) {
    const float* xs = xt + (size_t)s_self[r] * IN_F;
    float u = 0.0f;
    #pragma unroll 4
    for (int k = 0; k < IN_F; k++)
        u = fmaf(xs[k], W1s[(size_t)k * H1_N + col], u);
    const int   S    = typeA ? S1_N : S2_N;
    const float invS = typeA ? 0.2f : 0.5f;
    #pragma unroll 4
    for (int k = 0; k < IN_F; k++) {
        float m = 0.0f;
        for (int s = 0; s < S; s++)
            m += xt[(size_t)s_nbr[r * S + s] * IN_F + k];
        u = fmaf(m * invS, W1n[(size_t)k * H1_N + col], u);
    }
    return u >= thr;
}

// ============================================================================
// Kernel 0a: fold softmax(delay_w) + depthwise-conv SAME + time-mean into A[c][t].
// ============================================================================
__global__ void prepA_kernel(const float* __restrict__ delay_w,
                             const float* __restrict__ dwk) {
    int c = threadIdx.x;
    if (c >= H2_N) return;
    int g = c >> 3;
    float w0 = delay_w[g * 3 + 0], w1 = delay_w[g * 3 + 1], w2 = delay_w[g * 3 + 2];
    float mx = fmaxf(w0, fmaxf(w1, w2));
    float e0 = expf(w0 - mx), e1 = expf(w1 - mx), e2 = expf(w2 - mx);
    float inv = 1.0f / (e0 + e1 + e2);
    e0 *= inv; e1 *= inv; e2 *= inv;

    float coef[T_STEPS];
    #pragma unroll
    for (int tau = 0; tau < T_STEPS; tau++) {
        int kmin = (tau - 13 > 0) ? (tau - 13) : 0;
        int kmax = (tau + 2 < 4) ? (tau + 2) : 4;
        float s = 0.0f;
        for (int k = kmin; k <= kmax; k++) s += dwk[c * K_CONV + k];
        coef[tau] = s * (1.0f / (float)T_STEPS);
    }
    #pragma unroll
    for (int t = 0; t < T_STEPS; t++) {
        float a = 0.0f;
        if (t + 1 < T_STEPS) a += e0 * coef[t + 1];
        if (t + 3 < T_STEPS) a += e1 * coef[t + 3];
        if (t + 5 < T_STEPS) a += e2 * coef[t + 5];
        g_A[c * T_STEPS + t] = a;
    }
}

// ============================================================================
// Kernel 0b: pre-split + transpose W1 into [n][k] tf32 hi/lo arrays.
// ============================================================================
__global__ void prepW1_kernel(const float* __restrict__ W1s,
                              const float* __restrict__ W1n) {
    int idx = blockIdx.x * 256 + threadIdx.x;   // 32768 total
    int n = idx & (H1_N - 1);
    int k = idx >> 7;
    float w = (k < IN_F) ? W1s[(size_t)k * H1_N + n]
                         : W1n[(size_t)(k - IN_F) * H1_N + n];
    float h = tf32r(w);
    g_W1hi[n * KTOT + k] = h;
    g_W1lo[n * KTOT + k] = tf32r(w - h);
}

// ============================================================================
// Kernel 1 (HYBRID): per-block engine choice.
//   (blk & 15) <  SCALAR_OF_16 : f32x2 scalar-pipe GEMM (validated R2 path)
//   else                       : tf32x3 mma.sync tensor-pipe GEMM + rescue (R5)
// Both: 128 rows x 128 cols, K=256. Co-resident CTAs overlap FMA + tensor pipes.
// dyn smem = 90112 B (max of the two layouts), 2 CTAs/SM.
// ============================================================================
__global__ void __launch_bounds__(256, 2)
layer1_hybrid(const float* __restrict__ x, const int* __restrict__ nodes,
              const int* __restrict__ nbr1, const int* __restrict__ nbr2,
              const float* __restrict__ b1,
              const float* __restrict__ W1s, const float* __restrict__ W1n) {
    extern __shared__ float sm[];
    __shared__ int s_self[128];
    __shared__ int s_nbr[128 * S1_N];
    __shared__ float s_thr[128];

    const int tid = threadIdx.x;
    const int wid = tid >> 5;
    const int lane = tid & 31;
    const int t = blockIdx.y;
    const int blk = blockIdx.x;               // 0..191
    const int typeA = (blk < (B_N / 128));
    const int rowbase = blk * 128;

    // ---- shared index + threshold stage ----
    if (tid < 128) s_thr[tid] = 1.0f - b1[tid];
    if (typeA) {
        if (tid < 128) s_self[tid] = nodes[rowbase + tid];
        for (int q = tid; q < 128 * S1_N; q += 256) {
            int r = q / S1_N, s = q - r * S1_N;
            s_nbr[q] = nbr1[((size_t)t * B_N + rowbase + r) * S1_N + s];
        }
    } else {
        const int j0 = rowbase - B_N;
        if (tid < 128) s_self[tid] = nbr1[(size_t)t * B_N * S1_N + j0 + tid];
        for (int q = tid; q < 128 * S2_N; q += 256) {
            int r = q >> 1, s = q & 1;
            s_nbr[q] = nbr2[((size_t)t * (B_N * S1_N) + j0 + r) * S2_N + s];
        }
    }

    const float* xt = x + (size_t)t * NNODES * IN_F;
    const int gr = tid >> 1;
    const int gq = (tid & 1) * 4;

    if ((blk & 15) < SCALAR_OF_16) {
        // ================= SCALAR f32x2 PATH (R2, validated) =================
        float* Zt = sm;                 // [64 k][128 r]
        float* Wt = sm + 64 * 128;      // [64 k][128 c]

        const int r0 = (tid & 15) * 8;
        const int c0 = (tid >> 4) * 8;

        ull acc[4][8];
        #pragma unroll
        for (int i = 0; i < 4; i++)
            #pragma unroll
            for (int j = 0; j < 8; j++) acc[i][j] = 0ull;

        for (int kt = 0; kt < 4; kt++) {
            __syncthreads();
            const int f0 = (kt & 1) * 64;
            if (kt < 2) {
                const float* src = xt + (size_t)s_self[gr] * IN_F + f0;
                #pragma unroll
                for (int w = 0; w < 8; w++) {
                    float4 v = *(const float4*)(src + (gq * 2 + w) * 4);
                    int k = (gq * 2 + w) * 4;
                    Zt[(k + 0) * 128 + gr] = v.x;
                    Zt[(k + 1) * 128 + gr] = v.y;
                    Zt[(k + 2) * 128 + gr] = v.z;
                    Zt[(k + 3) * 128 + gr] = v.w;
                }
            } else {
                const int   S    = typeA ? S1_N : S2_N;
                const float invS = typeA ? 0.2f : 0.5f;
                #pragma unroll
                for (int w = 0; w < 8; w++) {
                    float ax = 0.f, ay = 0.f, az = 0.f, aw = 0.f;
                    for (int s = 0; s < S; s++) {
                        float4 v = *(const float4*)(xt + (size_t)s_nbr[gr * S + s] * IN_F
                                                    + f0 + (gq * 2 + w) * 4);
                        ax += v.x; ay += v.y; az += v.z; aw += v.w;
                    }
                    int k = (gq * 2 + w) * 4;
                    Zt[(k + 0) * 128 + gr] = ax * invS;
                    Zt[(k + 1) * 128 + gr] = ay * invS;
                    Zt[(k + 2) * 128 + gr] = az * invS;
                    Zt[(k + 3) * 128 + gr] = aw * invS;
                }
            }
            for (int idx = tid; idx < 64 * 32; idx += 256) {
                int kr = idx >> 5, c4 = idx & 31;
                int kg = kt * 64 + kr;
                const float* srcw = (kg < IN_F) ? (W1s + (size_t)kg * H1_N)
                                                : (W1n + (size_t)(kg - IN_F) * H1_N);
                *(float4*)&Wt[kr * 128 + c4 * 4] = *(const float4*)(srcw + c4 * 4);
            }
            __syncthreads();

            #pragma unroll 4
            for (int k = 0; k < 64; k++) {
                const ull* za = (const ull*)&Zt[k * 128 + r0];
                ull a0 = za[0], a1 = za[1], a2 = za[2], a3 = za[3];
                float4 bA = *(const float4*)&Wt[k * 128 + c0];
                float4 bB = *(const float4*)&Wt[k * 128 + c0 + 4];
                ull bd[8];
                bd[0] = dup2(bA.x); bd[1] = dup2(bA.y);
                bd[2] = dup2(bA.z); bd[3] = dup2(bA.w);
                bd[4] = dup2(bB.x); bd[5] = dup2(bB.y);
                bd[6] = dup2(bB.z); bd[7] = dup2(bB.w);
                #pragma unroll
                for (int j = 0; j < 8; j++) {
                    acc[0][j] = fma2(a0, bd[j], acc[0][j]);
                    acc[1][j] = fma2(a1, bd[j], acc[1][j]);
                    acc[2][j] = fma2(a2, bd[j], acc[2][j]);
                    acc[3][j] = fma2(a3, bd[j], acc[3][j]);
                }
            }
        }

        float bb[8];
        #pragma unroll
        for (int j = 0; j < 8; j++) bb[j] = b1[c0 + j];
        #pragma unroll
        for (int i = 0; i < 4; i++) {
            int row = rowbase + r0 + 2 * i;
            ull pk0 = 0ull, pk1 = 0ull;
            #pragma unroll
            for (int j = 0; j < 8; j++) {
                if (lo2(acc[i][j]) + bb[j] >= 1.0f) pk0 |= (1ull << (8 * j));
                if (hi2(acc[i][j]) + bb[j] >= 1.0f) pk1 |= (1ull << (8 * j));
            }
            *(ull*)(g_s1 + ((size_t)t * R1 + row)     * H1_N + c0) = pk0;
            *(ull*)(g_s1 + ((size_t)t * R1 + row + 1) * H1_N + c0) = pk1;
        }
    } else {
        // ================= TENSOR tf32x3 + RESCUE PATH (R5, validated) ========
        float* Ah = sm;
        float* Al = Ah + 128 * APAD;
        float* Bh = Al + 128 * APAD;
        float* Bl = Bh + 128 * APAD;

        const int mbase = (wid & 3) * 32;
        const int nbase = (wid >> 2) * 64;
        const int g  = lane >> 2;
        const int tg = lane & 3;

        float acc[2][8][4];
        #pragma unroll
        for (int mt = 0; mt < 2; mt++)
            #pragma unroll
            for (int j = 0; j < 8; j++)
                #pragma unroll
                for (int c = 0; c < 4; c++) acc[mt][j][c] = 0.0f;

        const uint32_t* Ah_u = (const uint32_t*)Ah;
        const uint32_t* Al_u = (const uint32_t*)Al;
        const uint32_t* Bh_u = (const uint32_t*)Bh;
        const uint32_t* Bl_u = (const uint32_t*)Bl;

        for (int kc = 0; kc < 8; kc++) {
            __syncthreads();
            const int f0 = (kc & 3) * 32;
            if (kc < 4) {
                const float* src = xt + (size_t)s_self[gr] * IN_F + f0;
                #pragma unroll
                for (int i = 0; i < 4; i++) {
                    float4 v = *(const float4*)(src + (gq + i) * 4);
                    float hx = tf32r(v.x), hy = tf32r(v.y), hz = tf32r(v.z), hw = tf32r(v.w);
                    int o = gr * APAD + (gq + i) * 4;
                    *(float4*)(Ah + o) = make_float4(hx, hy, hz, hw);
                    *(float4*)(Al + o) = make_float4(tf32r(v.x - hx), tf32r(v.y - hy),
                                                     tf32r(v.z - hz), tf32r(v.w - hw));
                }
            } else {
                const int   S    = typeA ? S1_N : S2_N;
                const float invS = typeA ? 0.2f : 0.5f;
                #pragma unroll
                for (int i = 0; i < 4; i++) {
                    float ax = 0.f, ay = 0.f, az = 0.f, aw = 0.f;
                    for (int s = 0; s < S; s++) {
                        float4 v = *(const float4*)(xt + (size_t)s_nbr[gr * S + s] * IN_F
                                                    + f0 + (gq + i) * 4);
                        ax += v.x; ay += v.y; az += v.z; aw += v.w;
                    }
                    ax *= invS; ay *= invS; az *= invS; aw *= invS;
                    float hx = tf32r(ax), hy = tf32r(ay), hz = tf32r(az), hw = tf32r(aw);
                    int o = gr * APAD + (gq + i) * 4;
                    *(float4*)(Ah + o) = make_float4(hx, hy, hz, hw);
                    *(float4*)(Al + o) = make_float4(tf32r(ax - hx), tf32r(ay - hy),
                                                     tf32r(az - hz), tf32r(aw - hw));
                }
            }
            {
                const float* sh = g_W1hi + gr * KTOT + kc * 32;
                const float* sl = g_W1lo + gr * KTOT + kc * 32;
                #pragma unroll
                for (int i = 0; i < 4; i++) {
                    int o = gr * APAD + (gq + i) * 4;
                    *(float4*)(Bh + o) = *(const float4*)(sh + (gq + i) * 4);
                    *(float4*)(Bl + o) = *(const float4*)(sl + (gq + i) * 4);
                }
            }
            __syncthreads();

            #pragma unroll
            for (int k8 = 0; k8 < 4; k8++) {
                const int kb = k8 * 8;
                uint32_t ah[2][4], al[2][4];
                #pragma unroll
                for (int mt = 0; mt < 2; mt++) {
                    int r0 = (mbase + 16 * mt + g) * APAD + kb + tg;
                    int r8 = r0 + 8 * APAD;
                    ah[mt][0] = Ah_u[r0];     ah[mt][1] = Ah_u[r8];
                    ah[mt][2] = Ah_u[r0 + 4]; ah[mt][3] = Ah_u[r8 + 4];
                    al[mt][0] = Al_u[r0];     al[mt][1] = Al_u[r8];
                    al[mt][2] = Al_u[r0 + 4]; al[mt][3] = Al_u[r8 + 4];
                }
                #pragma unroll
                for (int j = 0; j < 8; j++) {
                    int bi = (nbase + 8 * j + g) * APAD + kb + tg;
                    uint32_t bh0 = Bh_u[bi], bh1 = Bh_u[bi + 4];
                    uint32_t bl0 = Bl_u[bi], bl1 = Bl_u[bi + 4];
                    #pragma unroll
                    for (int mt = 0; mt < 2; mt++) {
                        MMA_TF32(acc[mt][j], ah[mt], bh0, bh1);   // hh
                        MMA_TF32(acc[mt][j], ah[mt], bl0, bl1);   // hl
                        MMA_TF32(acc[mt][j], al[mt], bh0, bh1);   // lh
                    }
                }
            }
        }

        __syncthreads();
        uint8_t* sbytes = (uint8_t*)sm;
        #pragma unroll
        for (int mt = 0; mt < 2; mt++) {
            int R0 = mbase + 16 * mt + g;
            #pragma unroll
            for (int j = 0; j < 8; j++) {
                int C0 = nbase + 8 * j + 2 * tg;
                #pragma unroll
                for (int c = 0; c < 4; c++) {
                    int R = R0 + (c >> 1) * 8;
                    int C = C0 + (c & 1);
                    float thr = s_thr[C];
                    float d = acc[mt][j][c] - thr;
                    bool sp;
                    if (fabsf(d) < EPS_RESCUE) {
                        sp = rescue_dot(xt, s_self, s_nbr, typeA, R, C, W1s, W1n, thr);
                    } else {
                        sp = (d >= 0.0f);
                    }
                    sbytes[R * 128 + C] = sp ? 1 : 0;
                }
            }
        }
        __syncthreads();
        uint8_t* dst = g_s1 + ((size_t)t * R1 + rowbase) * H1_N;
        #pragma unroll
        for (int i = 0; i < 4; i++) {
            int o = (tid + i * 256) * 16;
            *(uint4*)(dst + o) = *(const uint4*)(sbytes + o);
        }
    }
}

// ============================================================================
// Kernel 2: layer-2 GEMM, packed fp32x2, W streamed from L1 (no smem staging).
// smem = Zt only (64 KB) -> 2 CTAs/SM (was 1).
// ============================================================================
__global__ void __launch_bounds__(256, 2)
layer2_kernel(const float* __restrict__ W2s, const float* __restrict__ W2n,
              const float* __restrict__ b2) {
    extern __shared__ float sm[];
    float* Zt = sm;                  // [256][64] k-major
    const int tid = threadIdx.x;
    const int t = blockIdx.y;
    const int b0 = blockIdx.x * 64;

    const uint8_t* s1t = g_s1 + (size_t)t * R1 * H1_N;
    const int r  = tid & 63;
    const int w0 = tid >> 6;
    for (int w = w0; w < 32; w += 4) {
        uint32_t gw = *(const uint32_t*)(s1t + (size_t)(b0 + r) * H1_N + w * 4);
        uint32_t mw = 0;   // bytes are 0/1; sum of 5 fits in a byte
        #pragma unroll
        for (int s = 0; s < S1_N; s++)
            mw += *(const uint32_t*)(s1t + (size_t)(B_N + (b0 + r) * S1_N + s) * H1_N + w * 4);
        int k = w * 4;
        Zt[(k + 0) * 64 + r] = (float)(gw & 0xffu);
        Zt[(k + 1) * 64 + r] = (float)((gw >> 8) & 0xffu);
        Zt[(k + 2) * 64 + r] = (float)((gw >> 16) & 0xffu);
        Zt[(k + 3) * 64 + r] = (float)(gw >> 24);
        Zt[(H1_N + k + 0) * 64 + r] = 0.2f * (float)(mw & 0xffu);
        Zt[(H1_N + k + 1) * 64 + r] = 0.2f * (float)((mw >> 8) & 0xffu);
        Zt[(H1_N + k + 2) * 64 + r] = 0.2f * (float)((mw >> 16) & 0xffu);
        Zt[(H1_N + k + 3) * 64 + r] = 0.2f * (float)(mw >> 24);
    }
    __syncthreads();

    const int r0 = (tid & 15) * 4;
    const int c0 = (tid >> 4) * 4;

    ull acc[2][4];
    #pragma unroll
    for (int i = 0; i < 2; i++)
        #pragma unroll
        for (int j = 0; j < 4; j++) acc[i][j] = 0ull;

    // k in [0,128): W2s ; k in [128,256): W2n — same order as before (bit-identical)
    #pragma unroll
    for (int h = 0; h < 2; h++) {
        const float* Wp = h ? W2n : W2s;
        const int kofs = h * H1_N;
        #pragma unroll 8
        for (int k = 0; k < 128; k++) {
            const ull* za = (const ull*)&Zt[(kofs + k) * 64 + r0];
            ull a0 = za[0], a1 = za[1];
            float4 b4 = *(const float4*)(Wp + (size_t)k * H2_N + c0);
            ull bd0 = dup2(b4.x), bd1 = dup2(b4.y), bd2 = dup2(b4.z), bd3 = dup2(b4.w);
            acc[0][0] = fma2(a0, bd0, acc[0][0]);
            acc[1][0] = fma2(a1, bd0, acc[1][0]);
            acc[0][1] = fma2(a0, bd1, acc[0][1]);
            acc[1][1] = fma2(a1, bd1, acc[1][1]);
            acc[0][2] = fma2(a0, bd2, acc[0][2]);
            acc[1][2] = fma2(a1, bd2, acc[1][2]);
            acc[0][3] = fma2(a0, bd3, acc[0][3]);
            acc[1][3] = fma2(a1, bd3, acc[1][3]);
        }
    }

    float bb[4];
    #pragma unroll
    for (int j = 0; j < 4; j++) bb[j] = b2[c0 + j];
    #pragma unroll
    for (int i = 0; i < 2; i++) {
        int b = b0 + r0 + 2 * i;
        uint32_t pk0 = 0, pk1 = 0;
        #pragma unroll
        for (int j = 0; j < 4; j++) {
            if (lo2(acc[i][j]) + bb[j] >= 1.0f) pk0 |= (1u << (8 * j));
            if (hi2(acc[i][j]) + bb[j] >= 1.0f) pk1 |= (1u << (8 * j));
        }
        *(uint32_t*)(g_s2 + ((size_t)t * B_N + b)     * H2_N + c0) = pk0;
        *(uint32_t*)(g_s2 + ((size_t)t * B_N + b + 1) * H2_N + c0) = pk1;
    }
}

// ============================================================================
// Kernel 3: readout. out[b,j] = ro_b[j] + sum_c (sum_t s2[t,b,c]*A[c,t]) ro_W[c,j]
// ============================================================================
__global__ void __launch_bounds__(256)
readout_kernel(const float* __restrict__ ro_W, const float* __restrict__ ro_b,
               float* __restrict__ out) {
    __shared__ float Msm[8][64];
    const int warp = threadIdx.x >> 5;
    const int lane = threadIdx.x & 31;
    const int b = blockIdx.x * 8 + warp;

    float m0 = 0.f, m1 = 0.f;
    #pragma unroll
    for (int t = 0; t < T_STEPS; t++) {
        const uint8_t* row = g_s2 + ((size_t)t * B_N + b) * H2_N;
        m0 = fmaf((float)row[lane],      g_A[lane * T_STEPS + t],        m0);
        m1 = fmaf((float)row[lane + 32], g_A[(lane + 32) * T_STEPS + t], m1);
    }
    Msm[warp][lane] = m0;
    Msm[warp][lane + 32] = m1;
    __syncwarp();

    float o = ro_b[lane];
    #pragma unroll
    for (int c = 0; c < 64; c++)
        o = fmaf(Msm[warp][c], ro_W[c * C_OUT + lane], o);
    out[(size_t)b * C_OUT + lane] = o;
}

// ============================================================================
extern "C" void kernel_launch(void* const* d_in, const int* in_sizes, int n_in,
                              void* d_out, int out_size) {
    const float* x    = (const float*)d_in[0];
    const int*   nodes= (const int*)  d_in[1];
    const int*   nbr1 = (const int*)  d_in[2];
    const int*   nbr2 = (const int*)  d_in[3];
    const float* W1s  = (const float*)d_in[4];
    const float* W1n  = (const float*)d_in[5];
    const float* b1   = (const float*)d_in[6];
    const float* W2s  = (const float*)d_in[7];
    const float* W2n  = (const float*)d_in[8];
    const float* b2   = (const float*)d_in[9];
    const float* dlw  = (const float*)d_in[10];
    const float* dwk  = (const float*)d_in[11];
    const float* roW  = (const float*)d_in[12];
    const float* rob  = (const float*)d_in[13];
    float* out = (float*)d_out;

    const int l1_smem = 4 * 128 * APAD * 4;   // 90112 B (tensor layout; scalar uses 64K of it)
    cudaFuncSetAttribute(layer1_hybrid, cudaFuncAttributeMaxDynamicSharedMemorySize, l1_smem);
    cudaFuncSetAttribute(layer2_kernel, cudaFuncAttributeMaxDynamicSharedMemorySize, 65536);

    prepA_kernel<<<1, 64>>>(dlw, dwk);
    prepW1_kernel<<<128, 256>>>(W1s, W1n);
    layer1_hybrid<<<dim3(R1 / 128, T_STEPS), 256, l1_smem>>>(x, nodes, nbr1, nbr2, b1, W1s, W1n);
    layer2_kernel<<<dim3(B_N / 64, T_STEPS), 256, 65536>>>(W2s, W2n, b2);
    readout_kernel<<<B_N / 8, 256>>>(roW, rob, out);
}